// round 7
// baseline (speedup 1.0000x reference)
#include <cuda_runtime.h>
#include <math.h>
#include <cstdint>

#define BB   2
#define SEQ  2048
#define DM   1024
#define NH   16
#define DKH  64
#define MTOT (BB*SEQ)   // 4096

// Scratch (allocation-free rule: __device__ globals)
__device__ float g_Q[(size_t)BB*NH*SEQ*DKH];   // [B,H,S,dk]  (tf32-rounded)
__device__ float g_K[(size_t)BB*NH*SEQ*DKH];
__device__ float g_V[(size_t)BB*NH*SEQ*DKH];
// g_AO double duty: (1) tf32-rounded copy of x for the QKV GEMM,
// (2) attention output afterwards. QKV GEMM finishes before attention writes.
__device__ float g_AO[(size_t)MTOT*DM];
__device__ float g_W[(size_t)4*DM*DM];         // rounded wq,wk,wv,wo

// ---------------------------------------------------------------------------
// helpers (plain PTX ISA only — compute_100 has no tcgen05)
// ---------------------------------------------------------------------------
__device__ __forceinline__ uint32_t smem_u32(const void* p) {
    uint32_t a;
    asm("{ .reg .u64 t; cvta.to.shared.u64 t, %1; cvt.u32.u64 %0, t; }" : "=r"(a) : "l"(p));
    return a;
}
__device__ __forceinline__ void cp16(uint32_t dst, const void* src) {
    asm volatile("cp.async.cg.shared.global [%0], [%1], 16;" :: "r"(dst), "l"(src));
}
__device__ __forceinline__ uint32_t f2tf(float f) {
    uint32_t r;
    asm("cvt.rna.tf32.f32 %0, %1;" : "=r"(r) : "f"(f));
    return r;
}
__device__ __forceinline__ void mma_tf32(float c[4],
    uint32_t a0, uint32_t a1, uint32_t a2, uint32_t a3, uint32_t b0, uint32_t b1) {
    asm volatile(
        "mma.sync.aligned.m16n8k8.row.col.f32.tf32.tf32.f32 "
        "{%0,%1,%2,%3}, {%4,%5,%6,%7}, {%8,%9}, {%0,%1,%2,%3};"
        : "+f"(c[0]), "+f"(c[1]), "+f"(c[2]), "+f"(c[3])
        : "r"(a0), "r"(a1), "r"(a2), "r"(a3), "r"(b0), "r"(b1));
}

// ---------------------------------------------------------------------------
// pre-pass: round fp32 -> tf32 (rna), stored back as fp32 with zero low bits.
// mma.sync consumes raw bits == identical math to cvt-at-load.
// ---------------------------------------------------------------------------
__global__ void round_tf32_kernel(const float* __restrict__ src, float* __restrict__ dst, int n4) {
    int i = blockIdx.x * blockDim.x + threadIdx.x;
    if (i < n4) {
        float4 v = ((const float4*)src)[i];
        v.x = __uint_as_float(f2tf(v.x));
        v.y = __uint_as_float(f2tf(v.y));
        v.z = __uint_as_float(f2tf(v.z));
        v.w = __uint_as_float(f2tf(v.w));
        ((float4*)dst)[i] = v;
    }
}

// ---------------------------------------------------------------------------
// tf32 mma.sync GEMM: C(128x256 per CTA) = A[M,K=1024] * W[N,K]^T
// Inputs pre-rounded to tf32 -> NO cvt in mainloop.
// 8 warps (2x4), 64x64 per warp. float2 fragment loads via k-slot remap:
// mma slots (lk, lk+4) hold columns (2lk, 2lk+1) on both A and B.
// remap=1: round outputs + scatter into [B,H,S,dk]. remap=0: plain [M,DM].
// ---------------------------------------------------------------------------
#define BK      16
#define GPITCH  20
#define GM      128
#define GN      256
#define A_FL    (GM*GPITCH)           // 2560
#define B_FL    (GN*GPITCH)           // 5120
#define STG_FL  (A_FL + B_FL)         // 7680
#define GSTAGES 3
#define GSMEM_B (GSTAGES*STG_FL*4)    // 92160
#define KTILES  (DM/BK)               // 64

__global__ void __launch_bounds__(256, 1) mma_gemm(
    const float* __restrict__ A,
    const float* __restrict__ W0, const float* __restrict__ W1, const float* __restrict__ W2,
    float* __restrict__ C0, float* __restrict__ C1, float* __restrict__ C2,
    int remap)
{
    extern __shared__ __align__(16) float sm[];
    const uint32_t sb = smem_u32(sm);

    const int tid  = threadIdx.x;
    const int wid  = tid >> 5, lane = tid & 31;
    const int wm   = wid >> 2, wn = wid & 3;       // 2x4 warps, 64x64 each
    const int lg   = lane >> 2;                    // 0..7
    const int lk   = lane & 3;                     // 0..3

    const float* W = (blockIdx.z == 0) ? W0 : (blockIdx.z == 1 ? W1 : W2);
    float*       C = (blockIdx.z == 0) ? C0 : (blockIdx.z == 1 ? C1 : C2);
    const int bm = blockIdx.y * GM;
    const int bn = blockIdx.x * GN;

    float acc[4][8][4];
#pragma unroll
    for (int i = 0; i < 4; i++)
#pragma unroll
        for (int j = 0; j < 8; j++)
#pragma unroll
            for (int k = 0; k < 4; k++) acc[i][j][k] = 0.0f;

    // loads: A rows 0..127 (2 thr/row, 8 floats), B rows 0..255 (1 thr/row, 16 floats)
    const int arow = tid >> 1;
    const int aq   = (tid & 1) * 8;

#define LOAD_STAGE(kt, s) do { \
        uint32_t _as = sb + (uint32_t)((s)*STG_FL)*4u; \
        uint32_t _bs = _as + (uint32_t)A_FL*4u; \
        const float* _ap = A + (size_t)(bm + arow) * DM + (kt)*BK + aq; \
        uint32_t _ad = _as + (uint32_t)(arow*GPITCH + aq)*4u; \
        cp16(_ad, _ap); cp16(_ad + 16, _ap + 4); \
        const float* _wp = W + (size_t)(bn + tid) * DM + (kt)*BK; \
        uint32_t _bd = _bs + (uint32_t)(tid*GPITCH)*4u; \
        cp16(_bd, _wp); cp16(_bd+16, _wp+4); cp16(_bd+32, _wp+8); cp16(_bd+48, _wp+12); \
    } while (0)

#define SA(s, r, k)  sm[(s)*STG_FL + (r)*GPITCH + (k)]
#define SB_(s, r, k) sm[(s)*STG_FL + A_FL + (r)*GPITCH + (k)]

#pragma unroll
    for (int s = 0; s < GSTAGES-1; s++) {
        LOAD_STAGE(s, s);
        asm volatile("cp.async.commit_group;" ::: "memory");
    }

    for (int kt = 0; kt < KTILES; kt++) {
        asm volatile("cp.async.wait_group %0;" :: "n"(GSTAGES-2) : "memory");
        __syncthreads();

        int knext = kt + GSTAGES - 1;
        if (knext < KTILES) LOAD_STAGE(knext, knext % GSTAGES);
        asm volatile("cp.async.commit_group;" ::: "memory");

        const int s = kt % GSTAGES;
#pragma unroll
        for (int k0 = 0; k0 < BK; k0 += 8) {
            const int kc = k0 + 2*lk;
            uint32_t af[4][4], bf[8][2];
#pragma unroll
            for (int tm = 0; tm < 4; tm++) {
                int r = wm*64 + tm*16 + lg;
                float2 qa = *(const float2*)&SA(s, r,   kc);
                float2 qb = *(const float2*)&SA(s, r+8, kc);
                af[tm][0] = __float_as_uint(qa.x);
                af[tm][1] = __float_as_uint(qb.x);
                af[tm][2] = __float_as_uint(qa.y);
                af[tm][3] = __float_as_uint(qb.y);
            }
#pragma unroll
            for (int tn = 0; tn < 8; tn++) {
                int c = wn*64 + tn*8 + lg;
                float2 kv = *(const float2*)&SB_(s, c, kc);
                bf[tn][0] = __float_as_uint(kv.x);
                bf[tn][1] = __float_as_uint(kv.y);
            }
#pragma unroll
            for (int tm = 0; tm < 4; tm++)
#pragma unroll
                for (int tn = 0; tn < 8; tn++)
                    mma_tf32(acc[tm][tn], af[tm][0], af[tm][1], af[tm][2], af[tm][3],
                             bf[tn][0], bf[tn][1]);
        }
        __syncthreads();
    }

    // epilogue
#pragma unroll
    for (int tm = 0; tm < 4; tm++) {
        int r0 = bm + wm*64 + tm*16 + lg;
        int r1 = r0 + 8;
#pragma unroll
        for (int tn = 0; tn < 8; tn++) {
            int c0 = bn + wn*64 + tn*8 + 2*lk;
            if (remap) {
                int b0v = r0 >> 11, s0 = r0 & (SEQ-1);
                int b1v = r1 >> 11, s1 = r1 & (SEQ-1);
                int h = c0 >> 6, d = c0 & (DKH-1);
                float* p0 = C + (((size_t)(b0v*NH + h) * SEQ) + s0) * DKH + d;
                float* p1 = C + (((size_t)(b1v*NH + h) * SEQ) + s1) * DKH + d;
                *(float2*)p0 = make_float2(__uint_as_float(f2tf(acc[tm][tn][0])),
                                           __uint_as_float(f2tf(acc[tm][tn][1])));
                *(float2*)p1 = make_float2(__uint_as_float(f2tf(acc[tm][tn][2])),
                                           __uint_as_float(f2tf(acc[tm][tn][3])));
            } else {
                float* p0 = C + (size_t)r0 * DM + c0;
                float* p1 = C + (size_t)r1 * DM + c0;
                *(float2*)p0 = make_float2(acc[tm][tn][0], acc[tm][tn][1]);
                *(float2*)p1 = make_float2(acc[tm][tn][2], acc[tm][tn][3]);
            }
        }
    }
#undef LOAD_STAGE
#undef SA
#undef SB_
}

// ---------------------------------------------------------------------------
// Causal flash attention on tf32 mma.sync. Q/K/V pre-rounded -> raw-bit frags.
// Only P (post-exp) and AO output need rounding.
// ---------------------------------------------------------------------------
#define QT      128
#define KT      64
#define APITCH  68
#define QS_OFF  0
#define KS_OFF  (QT*APITCH)
#define VS_OFF  (KS_OFF + 2*KT*APITCH)
#define PS_OFF  (VS_OFF + 2*KT*APITCH)
#define ASMEM_B ((PS_OFF + QT*APITCH)*4)       // 139264 bytes

__global__ void __launch_bounds__(256) attn_mma(
    const float* __restrict__ Qg, const float* __restrict__ Kg,
    const float* __restrict__ Vg, float* __restrict__ AO)
{
    extern __shared__ __align__(16) float asmem[];
    const uint32_t sb = smem_u32(asmem);

    const int tid = threadIdx.x;
    const int wid = tid >> 5, lane = tid & 31;
    const int lg = lane >> 2, lk = lane & 3;
    const int qt = gridDim.x - 1 - blockIdx.x;
    const int bh = blockIdx.y;
    const int b  = bh >> 4, h = bh & (NH-1);
    const float* Qb = Qg + (size_t)bh * SEQ * DKH;
    const float* Kb = Kg + (size_t)bh * SEQ * DKH;
    const float* Vb = Vg + (size_t)bh * SEQ * DKH;

#define QSV(r,c)   asmem[QS_OFF + (r)*APITCH + (c)]
#define KSV(s,r,c) asmem[KS_OFF + (s)*KT*APITCH + (r)*APITCH + (c)]
#define VSV(s,r,c) asmem[VS_OFF + (s)*KT*APITCH + (r)*APITCH + (c)]
#define PSV(r,c)   asmem[PS_OFF + (r)*APITCH + (c)]

    {
        int row = tid >> 1, cb = (tid & 1) * 32;
        const float* qp = Qb + (size_t)(qt*QT + row) * DKH + cb;
        uint32_t dst = sb + (uint32_t)(QS_OFF + row*APITCH + cb) * 4u;
#pragma unroll
        for (int i = 0; i < 8; i++) cp16(dst + i*16, qp + i*4);
    }

#define LOAD_KV(kt_, s_) do { \
        int _r = tid >> 2, _cb = (tid & 3) * 16; \
        const float* _kp = Kb + (size_t)((kt_)*KT + _r) * DKH + _cb; \
        const float* _vp = Vb + (size_t)((kt_)*KT + _r) * DKH + _cb; \
        uint32_t _kd = sb + (uint32_t)(KS_OFF + (s_)*KT*APITCH + _r*APITCH + _cb) * 4u; \
        uint32_t _vd = sb + (uint32_t)(VS_OFF + (s_)*KT*APITCH + _r*APITCH + _cb) * 4u; \
        _Pragma("unroll") \
        for (int _i = 0; _i < 4; _i++) { \
            cp16(_kd + _i*16, _kp + _i*4); \
            cp16(_vd + _i*16, _vp + _i*4); \
        } } while (0)

    LOAD_KV(0, 0);
    asm volatile("cp.async.commit_group;" ::: "memory");

    float m0 = -INFINITY, m1 = -INFINITY, l0 = 0.0f, l1 = 0.0f;
    float o[8][4];
#pragma unroll
    for (int tn = 0; tn < 8; tn++)
#pragma unroll
        for (int j = 0; j < 4; j++) o[tn][j] = 0.0f;

    const int ntiles = 2*qt + 2;
    const int r0 = qt*QT + wid*16 + lg;
    const int r1 = r0 + 8;
    const float scale = 0.125f;

    for (int kt = 0; kt < ntiles; kt++) {
        const int s = kt & 1;
        if (kt + 1 < ntiles) LOAD_KV(kt + 1, s ^ 1);
        asm volatile("cp.async.commit_group;" ::: "memory");
        asm volatile("cp.async.wait_group 1;" ::: "memory");
        __syncthreads();

        const bool active = (kt*KT <= qt*QT + wid*16 + 15);
        if (active) {
            float sc[8][4];
#pragma unroll
            for (int tn = 0; tn < 8; tn++)
#pragma unroll
                for (int j = 0; j < 4; j++) sc[tn][j] = 0.0f;

#pragma unroll
            for (int k0 = 0; k0 < DKH; k0 += 8) {
                float2 qa = *(const float2*)&QSV(wid*16 + lg,     k0 + 2*lk);
                float2 qb = *(const float2*)&QSV(wid*16 + lg + 8, k0 + 2*lk);
                uint32_t a0 = __float_as_uint(qa.x), a2 = __float_as_uint(qa.y);
                uint32_t a1 = __float_as_uint(qb.x), a3 = __float_as_uint(qb.y);
#pragma unroll
                for (int tn = 0; tn < 8; tn++) {
                    float2 kv = *(const float2*)&KSV(s, tn*8 + lg, k0 + 2*lk);
                    mma_tf32(sc[tn], a0, a1, a2, a3,
                             __float_as_uint(kv.x), __float_as_uint(kv.y));
                }
            }

#pragma unroll
            for (int tn = 0; tn < 8; tn++) {
                int c = kt*KT + tn*8 + 2*lk;
                sc[tn][0] = (c     > r0) ? -INFINITY : sc[tn][0]*scale;
                sc[tn][1] = (c + 1 > r0) ? -INFINITY : sc[tn][1]*scale;
                sc[tn][2] = (c     > r1) ? -INFINITY : sc[tn][2]*scale;
                sc[tn][3] = (c + 1 > r1) ? -INFINITY : sc[tn][3]*scale;
            }

            float mx0 = -INFINITY, mx1 = -INFINITY;
#pragma unroll
            for (int tn = 0; tn < 8; tn++) {
                mx0 = fmaxf(mx0, fmaxf(sc[tn][0], sc[tn][1]));
                mx1 = fmaxf(mx1, fmaxf(sc[tn][2], sc[tn][3]));
            }
#pragma unroll
            for (int off = 1; off < 4; off <<= 1) {
                mx0 = fmaxf(mx0, __shfl_xor_sync(0xffffffffu, mx0, off));
                mx1 = fmaxf(mx1, __shfl_xor_sync(0xffffffffu, mx1, off));
            }
            float nm0 = fmaxf(m0, mx0), nm1 = fmaxf(m1, mx1);
            float al0 = __expf(m0 - nm0), al1 = __expf(m1 - nm1);
            float s0 = 0.0f, s1 = 0.0f;
#pragma unroll
            for (int tn = 0; tn < 8; tn++) {
                sc[tn][0] = __expf(sc[tn][0] - nm0); s0 += sc[tn][0];
                sc[tn][1] = __expf(sc[tn][1] - nm0); s0 += sc[tn][1];
                sc[tn][2] = __expf(sc[tn][2] - nm1); s1 += sc[tn][2];
                sc[tn][3] = __expf(sc[tn][3] - nm1); s1 += sc[tn][3];
            }
#pragma unroll
            for (int off = 1; off < 4; off <<= 1) {
                s0 += __shfl_xor_sync(0xffffffffu, s0, off);
                s1 += __shfl_xor_sync(0xffffffffu, s1, off);
            }
            l0 = l0*al0 + s0; l1 = l1*al1 + s1;
            m0 = nm0; m1 = nm1;
#pragma unroll
            for (int tn = 0; tn < 8; tn++) {
                o[tn][0] *= al0; o[tn][1] *= al0;
                o[tn][2] *= al1; o[tn][3] *= al1;
            }

            // P -> warp-private smem (rounded to tf32 bits)
#pragma unroll
            for (int tn = 0; tn < 8; tn++) {
                *(float2*)&PSV(wid*16 + lg,     tn*8 + 2*lk) =
                    make_float2(__uint_as_float(f2tf(sc[tn][0])), __uint_as_float(f2tf(sc[tn][1])));
                *(float2*)&PSV(wid*16 + lg + 8, tn*8 + 2*lk) =
                    make_float2(__uint_as_float(f2tf(sc[tn][2])), __uint_as_float(f2tf(sc[tn][3])));
            }
            __syncwarp();

#pragma unroll
            for (int k0 = 0; k0 < KT; k0 += 8) {
                float2 pa = *(const float2*)&PSV(wid*16 + lg,     k0 + 2*lk);
                float2 pb = *(const float2*)&PSV(wid*16 + lg + 8, k0 + 2*lk);
                uint32_t a0 = __float_as_uint(pa.x), a2 = __float_as_uint(pa.y);
                uint32_t a1 = __float_as_uint(pb.x), a3 = __float_as_uint(pb.y);
#pragma unroll
                for (int tn = 0; tn < 8; tn++) {
                    uint32_t b0 = __float_as_uint(VSV(s, k0 + 2*lk,     tn*8 + lg));
                    uint32_t b1 = __float_as_uint(VSV(s, k0 + 2*lk + 1, tn*8 + lg));
                    mma_tf32(o[tn], a0, a1, a2, a3, b0, b1);
                }
            }
            __syncwarp();
        }
        __syncthreads();
    }

    // write normalized output (tf32-rounded for the O-projection)
    float inv0 = 1.0f / l0, inv1 = 1.0f / l1;
    float* base0 = AO + ((size_t)(b*SEQ + r0) * DM) + h*DKH;
    float* base1 = AO + ((size_t)(b*SEQ + r1) * DM) + h*DKH;
#pragma unroll
    for (int tn = 0; tn < 8; tn++) {
        int c = tn*8 + 2*lk;
        *(float2*)(base0 + c) = make_float2(__uint_as_float(f2tf(o[tn][0]*inv0)),
                                            __uint_as_float(f2tf(o[tn][1]*inv0)));
        *(float2*)(base1 + c) = make_float2(__uint_as_float(f2tf(o[tn][2]*inv1)),
                                            __uint_as_float(f2tf(o[tn][3]*inv1)));
    }
#undef LOAD_KV
#undef QSV
#undef KSV
#undef VSV
#undef PSV
}

// ---------------------------------------------------------------------------
extern "C" void kernel_launch(void* const* d_in, const int* in_sizes, int n_in,
                              void* d_out, int out_size)
{
    const float* x  = (const float*)d_in[0];
    const float* wq = (const float*)d_in[1];
    const float* wk = (const float*)d_in[2];
    const float* wv = (const float*)d_in[3];
    const float* wo = (const float*)d_in[4];

    float *Qp, *Kp, *Vp, *AOp, *Wp;
    cudaGetSymbolAddress((void**)&Qp,  g_Q);
    cudaGetSymbolAddress((void**)&Kp,  g_K);
    cudaGetSymbolAddress((void**)&Vp,  g_V);
    cudaGetSymbolAddress((void**)&AOp, g_AO);
    cudaGetSymbolAddress((void**)&Wp,  g_W);

    float* wqr = Wp;                          // 1M floats each
    float* wkr = Wp + (size_t)1*DM*DM;
    float* wvr = Wp + (size_t)2*DM*DM;
    float* wor = Wp + (size_t)3*DM*DM;
    float* xr  = AOp;                         // g_AO reused: rounded x lives here
                                              // until attention overwrites it

    static int attr_set = 0;
    if (!attr_set) {
        cudaFuncSetAttribute(mma_gemm, cudaFuncAttributeMaxDynamicSharedMemorySize, GSMEM_B);
        cudaFuncSetAttribute(attn_mma, cudaFuncAttributeMaxDynamicSharedMemorySize, ASMEM_B);
        attr_set = 1;
    }

    // pre-pass: tf32-round x (into g_AO) and the four weight matrices
    const int NX = MTOT*DM, NW = DM*DM;
    round_tf32_kernel<<<(NX/4 + 255)/256, 256>>>(x,  xr,  NX/4);
    round_tf32_kernel<<<(NW/4 + 255)/256, 256>>>(wq, wqr, NW/4);
    round_tf32_kernel<<<(NW/4 + 255)/256, 256>>>(wk, wkr, NW/4);
    round_tf32_kernel<<<(NW/4 + 255)/256, 256>>>(wv, wvr, NW/4);
    round_tf32_kernel<<<(NW/4 + 255)/256, 256>>>(wo, wor, NW/4);

    // QKV projections (cvt-free tf32 mma.sync), scatter+round to [B,H,S,dk]
    dim3 g1(DM/GN, MTOT/GM, 3);
    mma_gemm<<<g1, 256, GSMEM_B>>>(xr, wqr, wkr, wvr, Qp, Kp, Vp, 1);

    // Causal attention (tf32 mma.sync); overwrites g_AO with attention output
    dim3 g2(SEQ/QT, BB*NH, 1);
    attn_mma<<<g2, 256, ASMEM_B>>>(Qp, Kp, Vp, AOp);

    // Output projection -> d_out (plain fp32 store)
    dim3 g3(DM/GN, MTOT/GM, 1);
    mma_gemm<<<g3, 256, GSMEM_B>>>(AOp, wor, wor, wor,
                                   (float*)d_out, (float*)d_out, (float*)d_out, 0);
}

// round 8
// speedup vs baseline: 1.0647x; 1.0647x over previous
#include <cuda_runtime.h>
#include <math.h>
#include <cstdint>

#define BB   2
#define SEQ  2048
#define DM   1024
#define NH   16
#define DKH  64
#define MTOT (BB*SEQ)   // 4096

// Scratch (allocation-free rule: __device__ globals)
__device__ float g_Q[(size_t)BB*NH*SEQ*DKH];   // [B,H,S,dk]  (tf32-rounded)
__device__ float g_K[(size_t)BB*NH*SEQ*DKH];
__device__ float g_V[(size_t)BB*NH*SEQ*DKH];
// g_AO double duty: (1) tf32-rounded x for the QKV GEMM, (2) attention output.
__device__ float g_AO[(size_t)MTOT*DM];
__device__ float g_W[(size_t)4*DM*DM];         // rounded wq,wk,wv,wo

// ---------------------------------------------------------------------------
__device__ __forceinline__ uint32_t smem_u32(const void* p) {
    uint32_t a;
    asm("{ .reg .u64 t; cvta.to.shared.u64 t, %1; cvt.u32.u64 %0, t; }" : "=r"(a) : "l"(p));
    return a;
}
__device__ __forceinline__ void cp16(uint32_t dst, const void* src) {
    asm volatile("cp.async.cg.shared.global [%0], [%1], 16;" :: "r"(dst), "l"(src));
}
__device__ __forceinline__ uint32_t f2tf(float f) {
    uint32_t r;
    asm("cvt.rna.tf32.f32 %0, %1;" : "=r"(r) : "f"(f));
    return r;
}
__device__ __forceinline__ void mma_tf32(float c[4],
    uint32_t a0, uint32_t a1, uint32_t a2, uint32_t a3, uint32_t b0, uint32_t b1) {
    asm volatile(
        "mma.sync.aligned.m16n8k8.row.col.f32.tf32.tf32.f32 "
        "{%0,%1,%2,%3}, {%4,%5,%6,%7}, {%8,%9}, {%0,%1,%2,%3};"
        : "+f"(c[0]), "+f"(c[1]), "+f"(c[2]), "+f"(c[3])
        : "r"(a0), "r"(a1), "r"(a2), "r"(a3), "r"(b0), "r"(b1));
}

// ---------------------------------------------------------------------------
// pre-pass: round fp32 -> tf32 (rna) stored as fp32. mma.sync consumes raw
// bits == identical math to cvt-at-load (validated: rel_err matched R4 exactly).
// ---------------------------------------------------------------------------
__global__ void round_tf32_kernel(const float* __restrict__ src, float* __restrict__ dst, int n4) {
    int i = blockIdx.x * blockDim.x + threadIdx.x;
    if (i < n4) {
        float4 v = ((const float4*)src)[i];
        v.x = __uint_as_float(f2tf(v.x));
        v.y = __uint_as_float(f2tf(v.y));
        v.z = __uint_as_float(f2tf(v.z));
        v.w = __uint_as_float(f2tf(v.w));
        ((float4*)dst)[i] = v;
    }
}

// ---------------------------------------------------------------------------
// tf32 mma.sync GEMM: C(128x128/CTA) = A[M,K=1024] * W[N,K]^T
// R4's proven 8-warp (2x4), 64x32-per-warp structure; cvt-free mainloop;
// float2 fragment loads via k-slot remap (slots (lk,lk+4) = cols (2lk,2lk+1)).
// ---------------------------------------------------------------------------
#define BK      16
#define PITCH   20
#define GSTAGES 3
#define STG_FL  (2*128*PITCH)
#define GSMEM_B (GSTAGES*STG_FL*4)    // 61440
#define KTILES  (DM/BK)               // 64

__global__ void __launch_bounds__(256) mma_gemm(
    const float* __restrict__ A,
    const float* __restrict__ W0, const float* __restrict__ W1, const float* __restrict__ W2,
    float* __restrict__ C0, float* __restrict__ C1, float* __restrict__ C2,
    int remap)
{
    extern __shared__ __align__(16) float sm[];
    const uint32_t sb = smem_u32(sm);

    const int tid  = threadIdx.x;
    const int wid  = tid >> 5, lane = tid & 31;
    const int wm   = wid >> 2, wn = wid & 3;       // 2x4 warps, 64x32 each
    const int lg   = lane >> 2;
    const int lk   = lane & 3;

    const float* W = (blockIdx.z == 0) ? W0 : (blockIdx.z == 1 ? W1 : W2);
    float*       C = (blockIdx.z == 0) ? C0 : (blockIdx.z == 1 ? C1 : C2);
    const int bm = blockIdx.y * 128;
    const int bn = blockIdx.x * 128;

    float acc[4][4][4];
#pragma unroll
    for (int i = 0; i < 4; i++)
#pragma unroll
        for (int j = 0; j < 4; j++)
#pragma unroll
            for (int k = 0; k < 4; k++) acc[i][j][k] = 0.0f;

    const int lrow = tid >> 2;
    const int lq   = (tid & 3) * 4;

#define LOAD_STAGE(kt, s) do { \
        uint32_t _as = sb + (uint32_t)((s)*STG_FL)*4u; \
        uint32_t _bs = _as + (uint32_t)(128*PITCH)*4u; \
        const float* _ap = A + (size_t)(bm + lrow) * DM + (kt)*BK + lq; \
        const float* _wp = W + (size_t)(bn + lrow) * DM + (kt)*BK + lq; \
        cp16(_as + (uint32_t)(lrow*PITCH + lq)*4u, _ap); \
        cp16(_bs + (uint32_t)(lrow*PITCH + lq)*4u, _wp); \
        cp16(_as + (uint32_t)((lrow+64)*PITCH + lq)*4u, _ap + (size_t)64*DM); \
        cp16(_bs + (uint32_t)((lrow+64)*PITCH + lq)*4u, _wp + (size_t)64*DM); \
    } while (0)

#define SA(s, r, k)  sm[(s)*STG_FL + (r)*PITCH + (k)]
#define SB_(s, r, k) sm[(s)*STG_FL + 128*PITCH + (r)*PITCH + (k)]

#pragma unroll
    for (int s = 0; s < GSTAGES-1; s++) {
        LOAD_STAGE(s, s);
        asm volatile("cp.async.commit_group;" ::: "memory");
    }

    for (int kt = 0; kt < KTILES; kt++) {
        asm volatile("cp.async.wait_group %0;" :: "n"(GSTAGES-2) : "memory");
        __syncthreads();

        int knext = kt + GSTAGES - 1;
        if (knext < KTILES) LOAD_STAGE(knext, knext % GSTAGES);
        asm volatile("cp.async.commit_group;" ::: "memory");

        const int s = kt % GSTAGES;
#pragma unroll
        for (int k0 = 0; k0 < BK; k0 += 8) {
            const int kc = k0 + 2*lk;
            uint32_t af[4][4], bf[4][2];
#pragma unroll
            for (int tm = 0; tm < 4; tm++) {
                int r = wm*64 + tm*16 + lg;
                float2 qa = *(const float2*)&SA(s, r,   kc);
                float2 qb = *(const float2*)&SA(s, r+8, kc);
                af[tm][0] = __float_as_uint(qa.x);
                af[tm][1] = __float_as_uint(qb.x);
                af[tm][2] = __float_as_uint(qa.y);
                af[tm][3] = __float_as_uint(qb.y);
            }
#pragma unroll
            for (int tn = 0; tn < 4; tn++) {
                int c = wn*32 + tn*8 + lg;
                float2 kv = *(const float2*)&SB_(s, c, kc);
                bf[tn][0] = __float_as_uint(kv.x);
                bf[tn][1] = __float_as_uint(kv.y);
            }
#pragma unroll
            for (int tm = 0; tm < 4; tm++)
#pragma unroll
                for (int tn = 0; tn < 4; tn++)
                    mma_tf32(acc[tm][tn], af[tm][0], af[tm][1], af[tm][2], af[tm][3],
                             bf[tn][0], bf[tn][1]);
        }
        __syncthreads();
    }

#pragma unroll
    for (int tm = 0; tm < 4; tm++) {
        int r0 = bm + wm*64 + tm*16 + lg;
        int r1 = r0 + 8;
#pragma unroll
        for (int tn = 0; tn < 4; tn++) {
            int c0 = bn + wn*32 + tn*8 + 2*lk;
            if (remap) {
                int b0v = r0 >> 11, s0 = r0 & (SEQ-1);
                int b1v = r1 >> 11, s1 = r1 & (SEQ-1);
                int h = c0 >> 6, d = c0 & (DKH-1);
                float* p0 = C + (((size_t)(b0v*NH + h) * SEQ) + s0) * DKH + d;
                float* p1 = C + (((size_t)(b1v*NH + h) * SEQ) + s1) * DKH + d;
                *(float2*)p0 = make_float2(__uint_as_float(f2tf(acc[tm][tn][0])),
                                           __uint_as_float(f2tf(acc[tm][tn][1])));
                *(float2*)p1 = make_float2(__uint_as_float(f2tf(acc[tm][tn][2])),
                                           __uint_as_float(f2tf(acc[tm][tn][3])));
            } else {
                float* p0 = C + (size_t)r0 * DM + c0;
                float* p1 = C + (size_t)r1 * DM + c0;
                *(float2*)p0 = make_float2(acc[tm][tn][0], acc[tm][tn][1]);
                *(float2*)p1 = make_float2(acc[tm][tn][2], acc[tm][tn][3]);
            }
        }
    }
#undef LOAD_STAGE
#undef SA
#undef SB_
}

// ---------------------------------------------------------------------------
// Causal flash attention on tf32 mma.sync (cvt-free; unchanged from R7 pass)
// ---------------------------------------------------------------------------
#define QT      128
#define KT      64
#define APITCH  68
#define QS_OFF  0
#define KS_OFF  (QT*APITCH)
#define VS_OFF  (KS_OFF + 2*KT*APITCH)
#define PS_OFF  (VS_OFF + 2*KT*APITCH)
#define ASMEM_B ((PS_OFF + QT*APITCH)*4)       // 139264 bytes

__global__ void __launch_bounds__(256) attn_mma(
    const float* __restrict__ Qg, const float* __restrict__ Kg,
    const float* __restrict__ Vg, float* __restrict__ AO)
{
    extern __shared__ __align__(16) float asmem[];
    const uint32_t sb = smem_u32(asmem);

    const int tid = threadIdx.x;
    const int wid = tid >> 5, lane = tid & 31;
    const int lg = lane >> 2, lk = lane & 3;
    const int qt = gridDim.x - 1 - blockIdx.x;
    const int bh = blockIdx.y;
    const int b  = bh >> 4, h = bh & (NH-1);
    const float* Qb = Qg + (size_t)bh * SEQ * DKH;
    const float* Kb = Kg + (size_t)bh * SEQ * DKH;
    const float* Vb = Vg + (size_t)bh * SEQ * DKH;

#define QSV(r,c)   asmem[QS_OFF + (r)*APITCH + (c)]
#define KSV(s,r,c) asmem[KS_OFF + (s)*KT*APITCH + (r)*APITCH + (c)]
#define VSV(s,r,c) asmem[VS_OFF + (s)*KT*APITCH + (r)*APITCH + (c)]
#define PSV(r,c)   asmem[PS_OFF + (r)*APITCH + (c)]

    {
        int row = tid >> 1, cb = (tid & 1) * 32;
        const float* qp = Qb + (size_t)(qt*QT + row) * DKH + cb;
        uint32_t dst = sb + (uint32_t)(QS_OFF + row*APITCH + cb) * 4u;
#pragma unroll
        for (int i = 0; i < 8; i++) cp16(dst + i*16, qp + i*4);
    }

#define LOAD_KV(kt_, s_) do { \
        int _r = tid >> 2, _cb = (tid & 3) * 16; \
        const float* _kp = Kb + (size_t)((kt_)*KT + _r) * DKH + _cb; \
        const float* _vp = Vb + (size_t)((kt_)*KT + _r) * DKH + _cb; \
        uint32_t _kd = sb + (uint32_t)(KS_OFF + (s_)*KT*APITCH + _r*APITCH + _cb) * 4u; \
        uint32_t _vd = sb + (uint32_t)(VS_OFF + (s_)*KT*APITCH + _r*APITCH + _cb) * 4u; \
        _Pragma("unroll") \
        for (int _i = 0; _i < 4; _i++) { \
            cp16(_kd + _i*16, _kp + _i*4); \
            cp16(_vd + _i*16, _vp + _i*4); \
        } } while (0)

    LOAD_KV(0, 0);
    asm volatile("cp.async.commit_group;" ::: "memory");

    float m0 = -INFINITY, m1 = -INFINITY, l0 = 0.0f, l1 = 0.0f;
    float o[8][4];
#pragma unroll
    for (int tn = 0; tn < 8; tn++)
#pragma unroll
        for (int j = 0; j < 4; j++) o[tn][j] = 0.0f;

    const int ntiles = 2*qt + 2;
    const int r0 = qt*QT + wid*16 + lg;
    const int r1 = r0 + 8;
    const float scale = 0.125f;

    for (int kt = 0; kt < ntiles; kt++) {
        const int s = kt & 1;
        if (kt + 1 < ntiles) LOAD_KV(kt + 1, s ^ 1);
        asm volatile("cp.async.commit_group;" ::: "memory");
        asm volatile("cp.async.wait_group 1;" ::: "memory");
        __syncthreads();

        const bool active = (kt*KT <= qt*QT + wid*16 + 15);
        if (active) {
            float sc[8][4];
#pragma unroll
            for (int tn = 0; tn < 8; tn++)
#pragma unroll
                for (int j = 0; j < 4; j++) sc[tn][j] = 0.0f;

#pragma unroll
            for (int k0 = 0; k0 < DKH; k0 += 8) {
                float2 qa = *(const float2*)&QSV(wid*16 + lg,     k0 + 2*lk);
                float2 qb = *(const float2*)&QSV(wid*16 + lg + 8, k0 + 2*lk);
                uint32_t a0 = __float_as_uint(qa.x), a2 = __float_as_uint(qa.y);
                uint32_t a1 = __float_as_uint(qb.x), a3 = __float_as_uint(qb.y);
#pragma unroll
                for (int tn = 0; tn < 8; tn++) {
                    float2 kv = *(const float2*)&KSV(s, tn*8 + lg, k0 + 2*lk);
                    mma_tf32(sc[tn], a0, a1, a2, a3,
                             __float_as_uint(kv.x), __float_as_uint(kv.y));
                }
            }

#pragma unroll
            for (int tn = 0; tn < 8; tn++) {
                int c = kt*KT + tn*8 + 2*lk;
                sc[tn][0] = (c     > r0) ? -INFINITY : sc[tn][0]*scale;
                sc[tn][1] = (c + 1 > r0) ? -INFINITY : sc[tn][1]*scale;
                sc[tn][2] = (c     > r1) ? -INFINITY : sc[tn][2]*scale;
                sc[tn][3] = (c + 1 > r1) ? -INFINITY : sc[tn][3]*scale;
            }

            float mx0 = -INFINITY, mx1 = -INFINITY;
#pragma unroll
            for (int tn = 0; tn < 8; tn++) {
                mx0 = fmaxf(mx0, fmaxf(sc[tn][0], sc[tn][1]));
                mx1 = fmaxf(mx1, fmaxf(sc[tn][2], sc[tn][3]));
            }
#pragma unroll
            for (int off = 1; off < 4; off <<= 1) {
                mx0 = fmaxf(mx0, __shfl_xor_sync(0xffffffffu, mx0, off));
                mx1 = fmaxf(mx1, __shfl_xor_sync(0xffffffffu, mx1, off));
            }
            float nm0 = fmaxf(m0, mx0), nm1 = fmaxf(m1, mx1);
            float al0 = __expf(m0 - nm0), al1 = __expf(m1 - nm1);
            float s0 = 0.0f, s1 = 0.0f;
#pragma unroll
            for (int tn = 0; tn < 8; tn++) {
                sc[tn][0] = __expf(sc[tn][0] - nm0); s0 += sc[tn][0];
                sc[tn][1] = __expf(sc[tn][1] - nm0); s0 += sc[tn][1];
                sc[tn][2] = __expf(sc[tn][2] - nm1); s1 += sc[tn][2];
                sc[tn][3] = __expf(sc[tn][3] - nm1); s1 += sc[tn][3];
            }
#pragma unroll
            for (int off = 1; off < 4; off <<= 1) {
                s0 += __shfl_xor_sync(0xffffffffu, s0, off);
                s1 += __shfl_xor_sync(0xffffffffu, s1, off);
            }
            l0 = l0*al0 + s0; l1 = l1*al1 + s1;
            m0 = nm0; m1 = nm1;
#pragma unroll
            for (int tn = 0; tn < 8; tn++) {
                o[tn][0] *= al0; o[tn][1] *= al0;
                o[tn][2] *= al1; o[tn][3] *= al1;
            }

#pragma unroll
            for (int tn = 0; tn < 8; tn++) {
                *(float2*)&PSV(wid*16 + lg,     tn*8 + 2*lk) =
                    make_float2(__uint_as_float(f2tf(sc[tn][0])), __uint_as_float(f2tf(sc[tn][1])));
                *(float2*)&PSV(wid*16 + lg + 8, tn*8 + 2*lk) =
                    make_float2(__uint_as_float(f2tf(sc[tn][2])), __uint_as_float(f2tf(sc[tn][3])));
            }
            __syncwarp();

#pragma unroll
            for (int k0 = 0; k0 < KT; k0 += 8) {
                float2 pa = *(const float2*)&PSV(wid*16 + lg,     k0 + 2*lk);
                float2 pb = *(const float2*)&PSV(wid*16 + lg + 8, k0 + 2*lk);
                uint32_t a0 = __float_as_uint(pa.x), a2 = __float_as_uint(pa.y);
                uint32_t a1 = __float_as_uint(pb.x), a3 = __float_as_uint(pb.y);
#pragma unroll
                for (int tn = 0; tn < 8; tn++) {
                    uint32_t b0 = __float_as_uint(VSV(s, k0 + 2*lk,     tn*8 + lg));
                    uint32_t b1 = __float_as_uint(VSV(s, k0 + 2*lk + 1, tn*8 + lg));
                    mma_tf32(o[tn], a0, a1, a2, a3, b0, b1);
                }
            }
            __syncwarp();
        }
        __syncthreads();
    }

    float inv0 = 1.0f / l0, inv1 = 1.0f / l1;
    float* base0 = AO + ((size_t)(b*SEQ + r0) * DM) + h*DKH;
    float* base1 = AO + ((size_t)(b*SEQ + r1) * DM) + h*DKH;
#pragma unroll
    for (int tn = 0; tn < 8; tn++) {
        int c = tn*8 + 2*lk;
        *(float2*)(base0 + c) = make_float2(__uint_as_float(f2tf(o[tn][0]*inv0)),
                                            __uint_as_float(f2tf(o[tn][1]*inv0)));
        *(float2*)(base1 + c) = make_float2(__uint_as_float(f2tf(o[tn][2]*inv1)),
                                            __uint_as_float(f2tf(o[tn][3]*inv1)));
    }
#undef LOAD_KV
#undef QSV
#undef KSV
#undef VSV
#undef PSV
}

// ---------------------------------------------------------------------------
extern "C" void kernel_launch(void* const* d_in, const int* in_sizes, int n_in,
                              void* d_out, int out_size)
{
    const float* x  = (const float*)d_in[0];
    const float* wq = (const float*)d_in[1];
    const float* wk = (const float*)d_in[2];
    const float* wv = (const float*)d_in[3];
    const float* wo = (const float*)d_in[4];

    float *Qp, *Kp, *Vp, *AOp, *Wp;
    cudaGetSymbolAddress((void**)&Qp,  g_Q);
    cudaGetSymbolAddress((void**)&Kp,  g_K);
    cudaGetSymbolAddress((void**)&Vp,  g_V);
    cudaGetSymbolAddress((void**)&AOp, g_AO);
    cudaGetSymbolAddress((void**)&Wp,  g_W);

    float* wqr = Wp;
    float* wkr = Wp + (size_t)1*DM*DM;
    float* wvr = Wp + (size_t)2*DM*DM;
    float* wor = Wp + (size_t)3*DM*DM;
    float* xr  = AOp;   // rounded x lives in g_AO until attention overwrites it

    static int attr_set = 0;
    if (!attr_set) {
        cudaFuncSetAttribute(mma_gemm, cudaFuncAttributeMaxDynamicSharedMemorySize, GSMEM_B);
        cudaFuncSetAttribute(attn_mma, cudaFuncAttributeMaxDynamicSharedMemorySize, ASMEM_B);
        attr_set = 1;
    }

    const int NX = MTOT*DM, NW = DM*DM;
    round_tf32_kernel<<<(NX/4 + 255)/256, 256>>>(x,  xr,  NX/4);
    round_tf32_kernel<<<(NW/4 + 255)/256, 256>>>(wq, wqr, NW/4);
    round_tf32_kernel<<<(NW/4 + 255)/256, 256>>>(wk, wkr, NW/4);
    round_tf32_kernel<<<(NW/4 + 255)/256, 256>>>(wv, wvr, NW/4);
    round_tf32_kernel<<<(NW/4 + 255)/256, 256>>>(wo, wor, NW/4);

    // QKV projections (cvt-free tf32 mma.sync), scatter+round to [B,H,S,dk]
    dim3 g1(DM/128, MTOT/128, 3);
    mma_gemm<<<g1, 256, GSMEM_B>>>(xr, wqr, wkr, wvr, Qp, Kp, Vp, 1);

    // Causal attention (tf32 mma.sync)
    dim3 g2(SEQ/QT, BB*NH, 1);
    attn_mma<<<g2, 256, ASMEM_B>>>(Qp, Kp, Vp, AOp);

    // Output projection -> d_out
    dim3 g3(DM/128, MTOT/128, 1);
    mma_gemm<<<g3, 256, GSMEM_B>>>(AOp, wor, wor, wor,
                                   (float*)d_out, (float*)d_out, (float*)d_out, 0);
}

// round 9
// speedup vs baseline: 1.3154x; 1.2354x over previous
#include <cuda_runtime.h>
#include <math.h>
#include <cstdint>

#define BB   2
#define SEQ  2048
#define DM   1024
#define NH   16
#define DKH  64
#define MTOT (BB*SEQ)   // 4096

// Scratch (allocation-free rule: __device__ globals)
__device__ float g_Q[(size_t)BB*NH*SEQ*DKH];   // [B,H,S,dk] tf32-rounded by GEMM epilogue
__device__ float g_K[(size_t)BB*NH*SEQ*DKH];
__device__ float g_V[(size_t)BB*NH*SEQ*DKH];
__device__ float g_AO[(size_t)MTOT*DM];        // [B,S,H*dk]

// ---------------------------------------------------------------------------
__device__ __forceinline__ uint32_t smem_u32(const void* p) {
    uint32_t a;
    asm("{ .reg .u64 t; cvta.to.shared.u64 t, %1; cvt.u32.u64 %0, t; }" : "=r"(a) : "l"(p));
    return a;
}
__device__ __forceinline__ void cp16(uint32_t dst, const void* src) {
    asm volatile("cp.async.cg.shared.global [%0], [%1], 16;" :: "r"(dst), "l"(src));
}
__device__ __forceinline__ uint32_t f2tf(float f) {
    uint32_t r;
    asm("cvt.rna.tf32.f32 %0, %1;" : "=r"(r) : "f"(f));
    return r;
}
__device__ __forceinline__ void mma_tf32(float c[4],
    uint32_t a0, uint32_t a1, uint32_t a2, uint32_t a3, uint32_t b0, uint32_t b1) {
    asm volatile(
        "mma.sync.aligned.m16n8k8.row.col.f32.tf32.tf32.f32 "
        "{%0,%1,%2,%3}, {%4,%5,%6,%7}, {%8,%9}, {%0,%1,%2,%3};"
        : "+f"(c[0]), "+f"(c[1]), "+f"(c[2]), "+f"(c[3])
        : "r"(a0), "r"(a1), "r"(a2), "r"(a3), "r"(b0), "r"(b1));
}

// ---------------------------------------------------------------------------
// tf32 mma.sync GEMM (R4-proven inner loop): C(128x128/CTA) = A * W^T
// 4-stage cp.async pipeline, ONE __syncthreads per k-iter.
// remap=1: scatter + tf32-round into [B,H,S,dk]. remap=0: plain [M,DM].
// ---------------------------------------------------------------------------
#define BK      16
#define PITCH   20
#define GSTAGES 4
#define STG_FL  (2*128*PITCH)
#define GSMEM_B (GSTAGES*STG_FL*4)    // 81920
#define KTILES  (DM/BK)               // 64

__global__ void __launch_bounds__(256) mma_gemm(
    const float* __restrict__ A,
    const float* __restrict__ W0, const float* __restrict__ W1, const float* __restrict__ W2,
    float* __restrict__ C0, float* __restrict__ C1, float* __restrict__ C2,
    int remap)
{
    extern __shared__ __align__(16) float sm[];
    const uint32_t sb = smem_u32(sm);

    const int tid  = threadIdx.x;
    const int wid  = tid >> 5, lane = tid & 31;
    const int wm   = wid >> 2, wn = wid & 3;       // 2x4 warps, 64x32 each
    const int lg   = lane >> 2;
    const int lk   = lane & 3;

    const float* W = (blockIdx.z == 0) ? W0 : (blockIdx.z == 1 ? W1 : W2);
    float*       C = (blockIdx.z == 0) ? C0 : (blockIdx.z == 1 ? C1 : C2);
    const int bm = blockIdx.y * 128;
    const int bn = blockIdx.x * 128;

    float acc[4][4][4];
#pragma unroll
    for (int i = 0; i < 4; i++)
#pragma unroll
        for (int j = 0; j < 4; j++)
#pragma unroll
            for (int k = 0; k < 4; k++) acc[i][j][k] = 0.0f;

    const int lrow = tid >> 2;
    const int lq   = (tid & 3) * 4;

#define LOAD_STAGE(kt, s) do { \
        uint32_t _as = sb + (uint32_t)((s)*STG_FL)*4u; \
        uint32_t _bs = _as + (uint32_t)(128*PITCH)*4u; \
        const float* _ap = A + (size_t)(bm + lrow) * DM + (kt)*BK + lq; \
        const float* _wp = W + (size_t)(bn + lrow) * DM + (kt)*BK + lq; \
        cp16(_as + (uint32_t)(lrow*PITCH + lq)*4u, _ap); \
        cp16(_bs + (uint32_t)(lrow*PITCH + lq)*4u, _wp); \
        cp16(_as + (uint32_t)((lrow+64)*PITCH + lq)*4u, _ap + (size_t)64*DM); \
        cp16(_bs + (uint32_t)((lrow+64)*PITCH + lq)*4u, _wp + (size_t)64*DM); \
    } while (0)

#define SA(s, r, k)  sm[(s)*STG_FL + (r)*PITCH + (k)]
#define SB_(s, r, k) sm[(s)*STG_FL + 128*PITCH + (r)*PITCH + (k)]

#pragma unroll
    for (int s = 0; s < GSTAGES-1; s++) {
        LOAD_STAGE(s, s);
        asm volatile("cp.async.commit_group;" ::: "memory");
    }

    for (int kt = 0; kt < KTILES; kt++) {
        asm volatile("cp.async.wait_group %0;" :: "n"(GSTAGES-2) : "memory");
        __syncthreads();   // single barrier: stage data visible + prior compute done

        int knext = kt + GSTAGES - 1;
        if (knext < KTILES) LOAD_STAGE(knext, knext % GSTAGES);
        asm volatile("cp.async.commit_group;" ::: "memory");

        const int s = kt % GSTAGES;
#pragma unroll
        for (int k0 = 0; k0 < BK; k0 += 8) {
            const int kr = k0 + lk;
            uint32_t af[4][4], bf[4][2];
#pragma unroll
            for (int tm = 0; tm < 4; tm++) {
                int r = wm*64 + tm*16 + lg;
                af[tm][0] = f2tf(SA(s, r,   kr));
                af[tm][1] = f2tf(SA(s, r+8, kr));
                af[tm][2] = f2tf(SA(s, r,   kr+4));
                af[tm][3] = f2tf(SA(s, r+8, kr+4));
            }
#pragma unroll
            for (int tn = 0; tn < 4; tn++) {
                int c = wn*32 + tn*8 + lg;
                bf[tn][0] = f2tf(SB_(s, c, kr));
                bf[tn][1] = f2tf(SB_(s, c, kr+4));
            }
#pragma unroll
            for (int tm = 0; tm < 4; tm++)
#pragma unroll
                for (int tn = 0; tn < 4; tn++)
                    mma_tf32(acc[tm][tn], af[tm][0], af[tm][1], af[tm][2], af[tm][3],
                             bf[tn][0], bf[tn][1]);
        }
    }

#pragma unroll
    for (int tm = 0; tm < 4; tm++) {
        int r0 = bm + wm*64 + tm*16 + lg;
        int r1 = r0 + 8;
#pragma unroll
        for (int tn = 0; tn < 4; tn++) {
            int c0 = bn + wn*32 + tn*8 + 2*lk;
            if (remap) {
                // tf32-round so attention consumes raw bits cvt-free
                int b0v = r0 >> 11, s0 = r0 & (SEQ-1);
                int b1v = r1 >> 11, s1 = r1 & (SEQ-1);
                int h = c0 >> 6, d = c0 & (DKH-1);
                float* p0 = C + (((size_t)(b0v*NH + h) * SEQ) + s0) * DKH + d;
                float* p1 = C + (((size_t)(b1v*NH + h) * SEQ) + s1) * DKH + d;
                *(float2*)p0 = make_float2(__uint_as_float(f2tf(acc[tm][tn][0])),
                                           __uint_as_float(f2tf(acc[tm][tn][1])));
                *(float2*)p1 = make_float2(__uint_as_float(f2tf(acc[tm][tn][2])),
                                           __uint_as_float(f2tf(acc[tm][tn][3])));
            } else {
                float* p0 = C + (size_t)r0 * DM + c0;
                float* p1 = C + (size_t)r1 * DM + c0;
                *(float2*)p0 = make_float2(acc[tm][tn][0], acc[tm][tn][1]);
                *(float2*)p1 = make_float2(acc[tm][tn][2], acc[tm][tn][3]);
            }
        }
    }
#undef LOAD_STAGE
#undef SA
#undef SB_
}

// ---------------------------------------------------------------------------
// Causal flash attention, tf32 mma.sync.
// Key changes vs R4: S C-fragment reused directly as PV A-fragment
// (c0,c1,c2,c3 -> a0,a2,a1,a3 under the k-slot remap) => NO P smem.
// Conflict-free pitches: Q/K 72 (float2: banks 8lg+2lk), V 68 (scalar: 8lk+lg).
// smem 106KB -> 2 CTAs/SM. One __syncthreads per KV tile.
// ---------------------------------------------------------------------------
#define QT      128
#define KT      64
#define QPITCH  72
#define VPITCH  68
#define QS_OFF  0
#define KS_OFF  (QT*QPITCH)                    // 9216
#define VS_OFF  (KS_OFF + 2*KT*QPITCH)         // 18432
#define ASMEM_B ((VS_OFF + 2*KT*VPITCH)*4)     // 108544 bytes

__global__ void __launch_bounds__(256, 2) attn_mma(
    const float* __restrict__ Qg, const float* __restrict__ Kg,
    const float* __restrict__ Vg, float* __restrict__ AO)
{
    extern __shared__ __align__(16) float asmem[];
    const uint32_t sb = smem_u32(asmem);

    const int tid = threadIdx.x;
    const int wid = tid >> 5, lane = tid & 31;
    const int lg = lane >> 2, lk = lane & 3;
    const int qt = gridDim.x - 1 - blockIdx.x;   // big tiles first
    const int bh = blockIdx.y;
    const int b  = bh >> 4, h = bh & (NH-1);
    const float* Qb = Qg + (size_t)bh * SEQ * DKH;
    const float* Kb = Kg + (size_t)bh * SEQ * DKH;
    const float* Vb = Vg + (size_t)bh * SEQ * DKH;

#define QSV(r,c)   asmem[QS_OFF + (r)*QPITCH + (c)]
#define KSV(s,r,c) asmem[KS_OFF + (s)*KT*QPITCH + (r)*QPITCH + (c)]
#define VSV(s,r,c) asmem[VS_OFF + (s)*KT*VPITCH + (r)*VPITCH + (c)]

    // load Q tile [128 x 64]
    {
        int row = tid >> 1, cb = (tid & 1) * 32;
        const float* qp = Qb + (size_t)(qt*QT + row) * DKH + cb;
        uint32_t dst = sb + (uint32_t)(QS_OFF + row*QPITCH + cb) * 4u;
#pragma unroll
        for (int i = 0; i < 8; i++) cp16(dst + i*16, qp + i*4);
    }

#define LOAD_KV(kt_, s_) do { \
        int _r = tid >> 2, _cb = (tid & 3) * 16; \
        const float* _kp = Kb + (size_t)((kt_)*KT + _r) * DKH + _cb; \
        const float* _vp = Vb + (size_t)((kt_)*KT + _r) * DKH + _cb; \
        uint32_t _kd = sb + (uint32_t)(KS_OFF + (s_)*KT*QPITCH + _r*QPITCH + _cb) * 4u; \
        uint32_t _vd = sb + (uint32_t)(VS_OFF + (s_)*KT*VPITCH + _r*VPITCH + _cb) * 4u; \
        _Pragma("unroll") \
        for (int _i = 0; _i < 4; _i++) { \
            cp16(_kd + _i*16, _kp + _i*4); \
            cp16(_vd + _i*16, _vp + _i*4); \
        } } while (0)

    LOAD_KV(0, 0);
    asm volatile("cp.async.commit_group;" ::: "memory");

    float m0 = -INFINITY, m1 = -INFINITY, l0 = 0.0f, l1 = 0.0f;
    float o[8][4];
#pragma unroll
    for (int tn = 0; tn < 8; tn++)
#pragma unroll
        for (int j = 0; j < 4; j++) o[tn][j] = 0.0f;

    const int ntiles = 2*qt + 2;
    const int r0 = qt*QT + wid*16 + lg;
    const int r1 = r0 + 8;
    const float scale = 0.125f;

    for (int kt = 0; kt < ntiles; kt++) {
        const int s = kt & 1;
        asm volatile("cp.async.wait_group 0;" ::: "memory");
        __syncthreads();   // buffer s data visible; all warps past compute(kt-1)

        if (kt + 1 < ntiles) LOAD_KV(kt + 1, s ^ 1);
        asm volatile("cp.async.commit_group;" ::: "memory");

        const bool active = (kt*KT <= qt*QT + wid*16 + 15);
        if (active) {
            // S = Q K^T  (Q/K pre-rounded -> raw-bit fragments)
            float sc[8][4];
#pragma unroll
            for (int tn = 0; tn < 8; tn++)
#pragma unroll
                for (int j = 0; j < 4; j++) sc[tn][j] = 0.0f;

#pragma unroll
            for (int k0 = 0; k0 < DKH; k0 += 8) {
                float2 qa = *(const float2*)&QSV(wid*16 + lg,     k0 + 2*lk);
                float2 qb = *(const float2*)&QSV(wid*16 + lg + 8, k0 + 2*lk);
                uint32_t a0 = __float_as_uint(qa.x), a2 = __float_as_uint(qa.y);
                uint32_t a1 = __float_as_uint(qb.x), a3 = __float_as_uint(qb.y);
#pragma unroll
                for (int tn = 0; tn < 8; tn++) {
                    float2 kv = *(const float2*)&KSV(s, tn*8 + lg, k0 + 2*lk);
                    mma_tf32(sc[tn], a0, a1, a2, a3,
                             __float_as_uint(kv.x), __float_as_uint(kv.y));
                }
            }

            // scale + causal mask
#pragma unroll
            for (int tn = 0; tn < 8; tn++) {
                int c = kt*KT + tn*8 + 2*lk;
                sc[tn][0] = (c     > r0) ? -INFINITY : sc[tn][0]*scale;
                sc[tn][1] = (c + 1 > r0) ? -INFINITY : sc[tn][1]*scale;
                sc[tn][2] = (c     > r1) ? -INFINITY : sc[tn][2]*scale;
                sc[tn][3] = (c + 1 > r1) ? -INFINITY : sc[tn][3]*scale;
            }

            // online softmax (rows in lane quads)
            float mx0 = -INFINITY, mx1 = -INFINITY;
#pragma unroll
            for (int tn = 0; tn < 8; tn++) {
                mx0 = fmaxf(mx0, fmaxf(sc[tn][0], sc[tn][1]));
                mx1 = fmaxf(mx1, fmaxf(sc[tn][2], sc[tn][3]));
            }
#pragma unroll
            for (int off = 1; off < 4; off <<= 1) {
                mx0 = fmaxf(mx0, __shfl_xor_sync(0xffffffffu, mx0, off));
                mx1 = fmaxf(mx1, __shfl_xor_sync(0xffffffffu, mx1, off));
            }
            float nm0 = fmaxf(m0, mx0), nm1 = fmaxf(m1, mx1);
            float al0 = __expf(m0 - nm0), al1 = __expf(m1 - nm1);
            float s0 = 0.0f, s1 = 0.0f;
#pragma unroll
            for (int tn = 0; tn < 8; tn++) {
                sc[tn][0] = __expf(sc[tn][0] - nm0); s0 += sc[tn][0];
                sc[tn][1] = __expf(sc[tn][1] - nm0); s0 += sc[tn][1];
                sc[tn][2] = __expf(sc[tn][2] - nm1); s1 += sc[tn][2];
                sc[tn][3] = __expf(sc[tn][3] - nm1); s1 += sc[tn][3];
            }
#pragma unroll
            for (int off = 1; off < 4; off <<= 1) {
                s0 += __shfl_xor_sync(0xffffffffu, s0, off);
                s1 += __shfl_xor_sync(0xffffffffu, s1, off);
            }
            l0 = l0*al0 + s0; l1 = l1*al1 + s1;
            m0 = nm0; m1 = nm1;
#pragma unroll
            for (int tn = 0; tn < 8; tn++) {
                o[tn][0] *= al0; o[tn][1] *= al0;
                o[tn][2] *= al1; o[tn][3] *= al1;
            }

            // O += P V : S C-fragment IS the PV A-fragment (a0,a1,a2,a3 = c0,c2,c1,c3)
#pragma unroll
            for (int tn = 0; tn < 8; tn++) {       // tn = 8-key k-chunk
                uint32_t a0 = f2tf(sc[tn][0]);
                uint32_t a1 = f2tf(sc[tn][2]);
                uint32_t a2 = f2tf(sc[tn][1]);
                uint32_t a3 = f2tf(sc[tn][3]);
#pragma unroll
                for (int tn2 = 0; tn2 < 8; tn2++) { // tn2 = 8-dim output tile
                    uint32_t b0 = __float_as_uint(VSV(s, tn*8 + 2*lk,     tn2*8 + lg));
                    uint32_t b1 = __float_as_uint(VSV(s, tn*8 + 2*lk + 1, tn2*8 + lg));
                    mma_tf32(o[tn2], a0, a1, a2, a3, b0, b1);
                }
            }
        }
    }

    // write normalized output into [B,S,H*dk]
    float inv0 = 1.0f / l0, inv1 = 1.0f / l1;
    float* base0 = AO + ((size_t)(b*SEQ + r0) * DM) + h*DKH;
    float* base1 = AO + ((size_t)(b*SEQ + r1) * DM) + h*DKH;
#pragma unroll
    for (int tn = 0; tn < 8; tn++) {
        int c = tn*8 + 2*lk;
        *(float2*)(base0 + c) = make_float2(o[tn][0]*inv0, o[tn][1]*inv0);
        *(float2*)(base1 + c) = make_float2(o[tn][2]*inv1, o[tn][3]*inv1);
    }
#undef LOAD_KV
#undef QSV
#undef KSV
#undef VSV
}

// ---------------------------------------------------------------------------
extern "C" void kernel_launch(void* const* d_in, const int* in_sizes, int n_in,
                              void* d_out, int out_size)
{
    const float* x  = (const float*)d_in[0];
    const float* wq = (const float*)d_in[1];
    const float* wk = (const float*)d_in[2];
    const float* wv = (const float*)d_in[3];
    const float* wo = (const float*)d_in[4];

    float *Qp, *Kp, *Vp, *AOp;
    cudaGetSymbolAddress((void**)&Qp,  g_Q);
    cudaGetSymbolAddress((void**)&Kp,  g_K);
    cudaGetSymbolAddress((void**)&Vp,  g_V);
    cudaGetSymbolAddress((void**)&AOp, g_AO);

    static int attr_set = 0;
    if (!attr_set) {
        cudaFuncSetAttribute(mma_gemm, cudaFuncAttributeMaxDynamicSharedMemorySize, GSMEM_B);
        cudaFuncSetAttribute(attn_mma, cudaFuncAttributeMaxDynamicSharedMemorySize, ASMEM_B);
        attr_set = 1;
    }

    // QKV projections (tf32 mma.sync), scatter + tf32-round to [B,H,S,dk]
    dim3 g1(DM/128, MTOT/128, 3);
    mma_gemm<<<g1, 256, GSMEM_B>>>(x, wq, wk, wv, Qp, Kp, Vp, 1);

    // Causal attention (tf32 mma.sync, register-P)
    dim3 g2(SEQ/QT, BB*NH, 1);
    attn_mma<<<g2, 256, ASMEM_B>>>(Qp, Kp, Vp, AOp);

    // Output projection -> d_out
    dim3 g3(DM/128, MTOT/128, 1);
    mma_gemm<<<g3, 256, GSMEM_B>>>(AOp, wo, wo, wo,
                                   (float*)d_out, (float*)d_out, (float*)d_out, 0);
}

// round 10
// speedup vs baseline: 2.3706x; 1.8023x over previous
#include <cuda_runtime.h>
#include <cuda_fp16.h>
#include <math.h>
#include <cstdint>

#define BB   2
#define SEQ  2048
#define DM   1024
#define NH   16
#define DKH  64
#define MTOT (BB*SEQ)   // 4096

// Scratch (allocation-free rule: __device__ globals)
__device__ __half g_xh[(size_t)MTOT*DM];     // fp16 x
__device__ __half g_wh[(size_t)4*DM*DM];     // fp16 wq,wk,wv,wo
__device__ __half g_Qh[(size_t)MTOT*DM];     // [B,H,S,dk], pre-scaled by 1/8
__device__ __half g_Kh[(size_t)MTOT*DM];     // [B,H,S,dk]
__device__ __half g_Vh[(size_t)MTOT*DM];     // [B,H,dk,S]  (TRANSPOSED)
__device__ __half g_AOh[(size_t)MTOT*DM];    // [B,S,H*dk]

// ---------------------------------------------------------------------------
__device__ __forceinline__ uint32_t smem_u32(const void* p) {
    uint32_t a;
    asm("{ .reg .u64 t; cvta.to.shared.u64 t, %1; cvt.u32.u64 %0, t; }" : "=r"(a) : "l"(p));
    return a;
}
__device__ __forceinline__ void cp16(uint32_t dst, const void* src) {
    asm volatile("cp.async.cg.shared.global [%0], [%1], 16;" :: "r"(dst), "l"(src));
}
__device__ __forceinline__ void mma_f16(float c[4],
    uint32_t a0, uint32_t a1, uint32_t a2, uint32_t a3, uint32_t b0, uint32_t b1) {
    asm volatile(
        "mma.sync.aligned.m16n8k16.row.col.f32.f16.f16.f32 "
        "{%0,%1,%2,%3}, {%4,%5,%6,%7}, {%8,%9}, {%0,%1,%2,%3};"
        : "+f"(c[0]), "+f"(c[1]), "+f"(c[2]), "+f"(c[3])
        : "r"(a0), "r"(a1), "r"(a2), "r"(a3), "r"(b0), "r"(b1));
}
__device__ __forceinline__ uint32_t packh2(float lo, float hi) {
    __half2 h = __floats2half2_rn(lo, hi);
    return *reinterpret_cast<uint32_t*>(&h);
}

// ---------------------------------------------------------------------------
// pre-pass: fp32 -> fp16
// ---------------------------------------------------------------------------
__global__ void f2h_kernel(const float* __restrict__ src, __half* __restrict__ dst, int n4) {
    int i = blockIdx.x * blockDim.x + threadIdx.x;
    if (i < n4) {
        float4 v = ((const float4*)src)[i];
        __half2* d = (__half2*)dst + (size_t)i*2;
        d[0] = __floats2half2_rn(v.x, v.y);
        d[1] = __floats2half2_rn(v.z, v.w);
    }
}

// ---------------------------------------------------------------------------
// fp16 mma.sync GEMM: C(128x128/CTA) = A[M,K=1024] * W[N,K]^T
// m16n8k16; k-slot remap: slot pairs = contiguous halves 4lk..4lk+3 on A and B
// => every fragment is one 8B load. BK=16 halves (32B rows, conflict-free).
// qkv=1: z selects Q (x1/8, [B,H,S,dk] h2) / K (same) / V (transposed scatter).
// qkv=0: fp32 row-major [M,DM] to C0v.
// ---------------------------------------------------------------------------
#define BK      16
#define GSTAGES 4
#define STG_HL  (2*128*BK)            // 4096 halves per stage
#define GSMEM_B (GSTAGES*STG_HL*2)    // 32768 B
#define KT16    (DM/BK)               // 64

__global__ void __launch_bounds__(256) hgemm(
    const __half* __restrict__ A,
    const __half* __restrict__ W0, const __half* __restrict__ W1, const __half* __restrict__ W2,
    void* C0v, void* C1v, void* C2v, int qkv)
{
    extern __shared__ __align__(16) __half hsm[];
    const uint32_t sb = smem_u32(hsm);

    const int tid  = threadIdx.x;
    const int wid  = tid >> 5, lane = tid & 31;
    const int wm   = wid >> 2, wn = wid & 3;       // 2x4 warps, 64x32 each
    const int lg   = lane >> 2;
    const int lk   = lane & 3;
    const int z    = blockIdx.z;

    const __half* W = (z == 0) ? W0 : (z == 1 ? W1 : W2);
    const int bm = blockIdx.y * 128;
    const int bn = blockIdx.x * 128;

    float acc[4][4][4];
#pragma unroll
    for (int i = 0; i < 4; i++)
#pragma unroll
        for (int j = 0; j < 4; j++)
#pragma unroll
            for (int k = 0; k < 4; k++) acc[i][j][k] = 0.0f;

    const int lrow = tid >> 1;            // 0..127
    const int lq   = (tid & 1) * 8;       // half offset 0 or 8

#define LOAD_STAGE(kt, s) do { \
        uint32_t _as = sb + (uint32_t)((s)*STG_HL)*2u; \
        uint32_t _bs = _as + (uint32_t)(128*BK)*2u; \
        cp16(_as + (uint32_t)(lrow*BK + lq)*2u, A + (size_t)(bm + lrow)*DM + (kt)*BK + lq); \
        cp16(_bs + (uint32_t)(lrow*BK + lq)*2u, W + (size_t)(bn + lrow)*DM + (kt)*BK + lq); \
    } while (0)

#pragma unroll
    for (int s = 0; s < GSTAGES-1; s++) {
        LOAD_STAGE(s, s);
        asm volatile("cp.async.commit_group;" ::: "memory");
    }

    const int kc = 4*lk;                  // half offset within BK row
    for (int kt = 0; kt < KT16; kt++) {
        asm volatile("cp.async.wait_group %0;" :: "n"(GSTAGES-2) : "memory");
        __syncthreads();

        int knext = kt + GSTAGES - 1;
        if (knext < KT16) LOAD_STAGE(knext, knext % GSTAGES);
        asm volatile("cp.async.commit_group;" ::: "memory");

        const int s = kt % GSTAGES;
        const __half* as = hsm + (size_t)s*STG_HL;
        const __half* bs = as + 128*BK;

        uint32_t af[4][4], bf[4][2];
#pragma unroll
        for (int tm = 0; tm < 4; tm++) {
            int r = wm*64 + tm*16 + lg;
            uint2 v0 = *(const uint2*)(as + r*BK + kc);
            uint2 v1 = *(const uint2*)(as + (r+8)*BK + kc);
            af[tm][0] = v0.x; af[tm][1] = v1.x; af[tm][2] = v0.y; af[tm][3] = v1.y;
        }
#pragma unroll
        for (int tn = 0; tn < 4; tn++) {
            int c = wn*32 + tn*8 + lg;
            uint2 u = *(const uint2*)(bs + c*BK + kc);
            bf[tn][0] = u.x; bf[tn][1] = u.y;
        }
#pragma unroll
        for (int tm = 0; tm < 4; tm++)
#pragma unroll
            for (int tn = 0; tn < 4; tn++)
                mma_f16(acc[tm][tn], af[tm][0], af[tm][1], af[tm][2], af[tm][3],
                        bf[tn][0], bf[tn][1]);
    }

    // epilogue
#pragma unroll
    for (int tm = 0; tm < 4; tm++) {
        int r0 = bm + wm*64 + tm*16 + lg;
        int r1 = r0 + 8;
#pragma unroll
        for (int tn = 0; tn < 4; tn++) {
            int c0 = bn + wn*32 + tn*8 + 2*lk;
            float v0 = acc[tm][tn][0], v1 = acc[tm][tn][1];
            float v2 = acc[tm][tn][2], v3 = acc[tm][tn][3];
            if (qkv) {
                int b0v = r0 >> 11, s0 = r0 & (SEQ-1);
                int b1v = r1 >> 11, s1 = r1 & (SEQ-1);
                int h = c0 >> 6, d = c0 & (DKH-1);
                if (z == 0) {          // Q: pre-scale by 1/8 (exact in fp16)
                    __half* C = (__half*)C0v;
                    *(__half2*)(C + (((size_t)(b0v*NH + h)*SEQ) + s0)*DKH + d) =
                        __floats2half2_rn(v0*0.125f, v1*0.125f);
                    *(__half2*)(C + (((size_t)(b1v*NH + h)*SEQ) + s1)*DKH + d) =
                        __floats2half2_rn(v2*0.125f, v3*0.125f);
                } else if (z == 1) {   // K
                    __half* C = (__half*)C1v;
                    *(__half2*)(C + (((size_t)(b0v*NH + h)*SEQ) + s0)*DKH + d) =
                        __floats2half2_rn(v0, v1);
                    *(__half2*)(C + (((size_t)(b1v*NH + h)*SEQ) + s1)*DKH + d) =
                        __floats2half2_rn(v2, v3);
                } else {               // V: transposed [B,H,dk,S]
                    __half* C = (__half*)C2v;
                    size_t base0 = ((size_t)(b0v*NH + h)*DKH + d)*SEQ;
                    size_t base1 = ((size_t)(b1v*NH + h)*DKH + d)*SEQ;
                    C[base0 + s0]       = __float2half_rn(v0);
                    C[base0 + SEQ + s0] = __float2half_rn(v1);
                    C[base1 + s1]       = __float2half_rn(v2);
                    C[base1 + SEQ + s1] = __float2half_rn(v3);
                }
            } else {
                float* C = (float*)C0v;
                *(float2*)(C + (size_t)r0*DM + c0) = make_float2(v0, v1);
                *(float2*)(C + (size_t)r1*DM + c0) = make_float2(v2, v3);
            }
        }
    }
#undef LOAD_STAGE
}

// ---------------------------------------------------------------------------
// Causal flash attention, fp16 mma.sync (m16n8k16).
// Q pre-scaled; V transposed in global so PV B-frags are contiguous half2.
// S C-frag packs directly into PV A-frag (no P smem). 1 syncthreads/tile.
// Pitches: Q/K 80 halves (160B ≡ 8 words: banks 8lg+2lk), V 72 (144B ≡ 4 words:
// banks 4lg+lk+8t) — conflict-free.
// ---------------------------------------------------------------------------
#define QP      80
#define VP      72
#define QS_OFF  0
#define KS_OFF  (128*QP)                 // 10240 halves
#define VS_OFF  (KS_OFF + 2*64*QP)       // 20480
#define ASMEM_H (VS_OFF + 2*64*VP)       // 29696 halves
#define ASMEM_B (ASMEM_H*2)              // 59392 B

__global__ void __launch_bounds__(256, 2) attn_h(
    const __half* __restrict__ Qg, const __half* __restrict__ Kg,
    const __half* __restrict__ Vg, __half* __restrict__ AO)
{
    extern __shared__ __align__(16) __half ash[];
    const uint32_t sb = smem_u32(ash);

    const int tid = threadIdx.x;
    const int wid = tid >> 5, lane = tid & 31;
    const int lg = lane >> 2, lk = lane & 3;
    const int qt = gridDim.x - 1 - blockIdx.x;     // big tiles first
    const int bh = blockIdx.y;
    const int b  = bh >> 4, h = bh & (NH-1);
    const __half* Qb = Qg + (size_t)bh * SEQ * DKH;
    const __half* Kb = Kg + (size_t)bh * SEQ * DKH;
    const __half* Vb = Vg + (size_t)bh * DKH * SEQ;   // [dk][S]

    // load Q tile [128 x 64]
    {
        int row = tid >> 1;
        int qq  = (tid & 1) * 4;
        const __half* qp = Qb + (size_t)(qt*128 + row) * DKH;
        uint32_t dst = sb + (uint32_t)(QS_OFF + row*QP)*2u;
#pragma unroll
        for (int i = 0; i < 4; i++)
            cp16(dst + (qq+i)*16, qp + (qq+i)*8);
    }

#define LOAD_KV(kt_, s_) do { \
        int _r = tid >> 2; \
        int _qi = (tid & 3) * 2; \
        const __half* _kp = Kb + (size_t)((kt_)*64 + _r) * DKH; \
        const __half* _vp = Vb + (size_t)_r * SEQ + (kt_)*64; \
        uint32_t _kd = sb + (uint32_t)(KS_OFF + (s_)*64*QP + _r*QP)*2u; \
        uint32_t _vd = sb + (uint32_t)(VS_OFF + (s_)*64*VP + _r*VP)*2u; \
        _Pragma("unroll") \
        for (int _i = 0; _i < 2; _i++) { \
            cp16(_kd + (_qi+_i)*16, _kp + (_qi+_i)*8); \
            cp16(_vd + (_qi+_i)*16, _vp + (_qi+_i)*8); \
        } } while (0)

    LOAD_KV(0, 0);
    asm volatile("cp.async.commit_group;" ::: "memory");

    float m0 = -INFINITY, m1 = -INFINITY, l0 = 0.0f, l1 = 0.0f;
    float o[8][4];
#pragma unroll
    for (int tn = 0; tn < 8; tn++)
#pragma unroll
        for (int j = 0; j < 4; j++) o[tn][j] = 0.0f;

    const int ntiles = 2*qt + 2;
    const int r0 = qt*128 + wid*16 + lg;
    const int r1 = r0 + 8;

    for (int kt = 0; kt < ntiles; kt++) {
        const int s = kt & 1;
        asm volatile("cp.async.wait_group 0;" ::: "memory");
        __syncthreads();

        if (kt + 1 < ntiles) LOAD_KV(kt + 1, s ^ 1);
        asm volatile("cp.async.commit_group;" ::: "memory");

        const bool active = (kt*64 <= qt*128 + wid*16 + 15);
        if (active) {
            // S = Q K^T (Q pre-scaled by 1/8)
            float sc[8][4];
#pragma unroll
            for (int tn = 0; tn < 8; tn++)
#pragma unroll
                for (int j = 0; j < 4; j++) sc[tn][j] = 0.0f;

            const __half* qsm = ash + QS_OFF;
            const __half* ksm = ash + KS_OFF + (size_t)s*64*QP;
#pragma unroll
            for (int k0 = 0; k0 < DKH; k0 += 16) {
                int kcc = k0 + 4*lk;
                uint2 qa = *(const uint2*)(qsm + (wid*16 + lg)*QP + kcc);
                uint2 qb = *(const uint2*)(qsm + (wid*16 + lg + 8)*QP + kcc);
#pragma unroll
                for (int tn = 0; tn < 8; tn++) {
                    uint2 kv = *(const uint2*)(ksm + (tn*8 + lg)*QP + kcc);
                    mma_f16(sc[tn], qa.x, qb.x, qa.y, qb.y, kv.x, kv.y);
                }
            }

            // causal mask (scores already scaled)
#pragma unroll
            for (int tn = 0; tn < 8; tn++) {
                int c = kt*64 + tn*8 + 2*lk;
                if (c     > r0) sc[tn][0] = -INFINITY;
                if (c + 1 > r0) sc[tn][1] = -INFINITY;
                if (c     > r1) sc[tn][2] = -INFINITY;
                if (c + 1 > r1) sc[tn][3] = -INFINITY;
            }

            // online softmax (rows in lane quads)
            float mx0 = -INFINITY, mx1 = -INFINITY;
#pragma unroll
            for (int tn = 0; tn < 8; tn++) {
                mx0 = fmaxf(mx0, fmaxf(sc[tn][0], sc[tn][1]));
                mx1 = fmaxf(mx1, fmaxf(sc[tn][2], sc[tn][3]));
            }
#pragma unroll
            for (int off = 1; off < 4; off <<= 1) {
                mx0 = fmaxf(mx0, __shfl_xor_sync(0xffffffffu, mx0, off));
                mx1 = fmaxf(mx1, __shfl_xor_sync(0xffffffffu, mx1, off));
            }
            float nm0 = fmaxf(m0, mx0), nm1 = fmaxf(m1, mx1);
            float al0 = __expf(m0 - nm0), al1 = __expf(m1 - nm1);
            float s0 = 0.0f, s1 = 0.0f;
#pragma unroll
            for (int tn = 0; tn < 8; tn++) {
                sc[tn][0] = __expf(sc[tn][0] - nm0); s0 += sc[tn][0];
                sc[tn][1] = __expf(sc[tn][1] - nm0); s0 += sc[tn][1];
                sc[tn][2] = __expf(sc[tn][2] - nm1); s1 += sc[tn][2];
                sc[tn][3] = __expf(sc[tn][3] - nm1); s1 += sc[tn][3];
            }
#pragma unroll
            for (int off = 1; off < 4; off <<= 1) {
                s0 += __shfl_xor_sync(0xffffffffu, s0, off);
                s1 += __shfl_xor_sync(0xffffffffu, s1, off);
            }
            l0 = l0*al0 + s0; l1 = l1*al1 + s1;
            m0 = nm0; m1 = nm1;
#pragma unroll
            for (int tn = 0; tn < 8; tn++) {
                o[tn][0] *= al0; o[tn][1] *= al0;
                o[tn][2] *= al1; o[tn][3] *= al1;
            }

            // O += P V : pack S C-frags to fp16 PV A-frags; V half2 contiguous
            const __half* vsm = ash + VS_OFF + (size_t)s*64*VP;
#pragma unroll
            for (int t = 0; t < 4; t++) {            // 16-key chunks
                uint32_t a0 = packh2(sc[2*t][0],   sc[2*t][1]);
                uint32_t a1 = packh2(sc[2*t][2],   sc[2*t][3]);
                uint32_t a2 = packh2(sc[2*t+1][0], sc[2*t+1][1]);
                uint32_t a3 = packh2(sc[2*t+1][2], sc[2*t+1][3]);
#pragma unroll
                for (int tn2 = 0; tn2 < 8; tn2++) {  // 8-dim output tiles
                    const __half* vrow = vsm + (tn2*8 + lg)*VP;
                    uint32_t b0 = *(const uint32_t*)(vrow + 16*t + 2*lk);
                    uint32_t b1 = *(const uint32_t*)(vrow + 16*t + 8 + 2*lk);
                    mma_f16(o[tn2], a0, a1, a2, a3, b0, b1);
                }
            }
        }
    }

    // write normalized output into [B,S,H*dk] as fp16
    float inv0 = 1.0f / l0, inv1 = 1.0f / l1;
    __half* base0 = AO + ((size_t)(b*SEQ + r0) * DM) + h*DKH;
    __half* base1 = AO + ((size_t)(b*SEQ + r1) * DM) + h*DKH;
#pragma unroll
    for (int tn = 0; tn < 8; tn++) {
        int c = tn*8 + 2*lk;
        *(__half2*)(base0 + c) = __floats2half2_rn(o[tn][0]*inv0, o[tn][1]*inv0);
        *(__half2*)(base1 + c) = __floats2half2_rn(o[tn][2]*inv1, o[tn][3]*inv1);
    }
#undef LOAD_KV
}

// ---------------------------------------------------------------------------
extern "C" void kernel_launch(void* const* d_in, const int* in_sizes, int n_in,
                              void* d_out, int out_size)
{
    const float* x  = (const float*)d_in[0];
    const float* wq = (const float*)d_in[1];
    const float* wk = (const float*)d_in[2];
    const float* wv = (const float*)d_in[3];
    const float* wo = (const float*)d_in[4];

    __half *xh, *wh, *Qh, *Kh, *Vh, *AOh;
    cudaGetSymbolAddress((void**)&xh,  g_xh);
    cudaGetSymbolAddress((void**)&wh,  g_wh);
    cudaGetSymbolAddress((void**)&Qh,  g_Qh);
    cudaGetSymbolAddress((void**)&Kh,  g_Kh);
    cudaGetSymbolAddress((void**)&Vh,  g_Vh);
    cudaGetSymbolAddress((void**)&AOh, g_AOh);

    __half* wqh = wh;
    __half* wkh = wh + (size_t)1*DM*DM;
    __half* wvh = wh + (size_t)2*DM*DM;
    __half* woh = wh + (size_t)3*DM*DM;

    static int attr_set = 0;
    if (!attr_set) {
        cudaFuncSetAttribute(hgemm,  cudaFuncAttributeMaxDynamicSharedMemorySize, GSMEM_B);
        cudaFuncSetAttribute(attn_h, cudaFuncAttributeMaxDynamicSharedMemorySize, ASMEM_B);
        attr_set = 1;
    }

    // pre-pass: fp32 -> fp16
    const int NX = MTOT*DM, NW = DM*DM;
    f2h_kernel<<<(NX/4 + 255)/256, 256>>>(x,  xh,  NX/4);
    f2h_kernel<<<(NW/4 + 255)/256, 256>>>(wq, wqh, NW/4);
    f2h_kernel<<<(NW/4 + 255)/256, 256>>>(wk, wkh, NW/4);
    f2h_kernel<<<(NW/4 + 255)/256, 256>>>(wv, wvh, NW/4);
    f2h_kernel<<<(NW/4 + 255)/256, 256>>>(wo, woh, NW/4);

    // QKV projections (fp16 mma), scatter Q(x1/8)/K/[V transposed]
    dim3 g1(DM/128, MTOT/128, 3);
    hgemm<<<g1, 256, GSMEM_B>>>(xh, wqh, wkh, wvh, Qh, Kh, Vh, 1);

    // Causal attention (fp16 mma)
    dim3 g2(SEQ/128, BB*NH, 1);
    attn_h<<<g2, 256, ASMEM_B>>>(Qh, Kh, Vh, AOh);

    // Output projection -> d_out (fp32 stores)
    dim3 g3(DM/128, MTOT/128, 1);
    hgemm<<<g3, 256, GSMEM_B>>>(AOh, woh, woh, woh,
                                (void*)d_out, (void*)d_out, (void*)d_out, 0);
}